// round 2
// baseline (speedup 1.0000x reference)
#include <cuda_runtime.h>
#include <math.h>

#define NMAX 34816
#define EMAX 557056
#define HD 64

__device__ float g_h[NMAX * HD];
__device__ float g_z[NMAX * HD];
__device__ float g_y[NMAX * HD];
__device__ int g_cnt[NMAX];
__device__ int g_off[NMAX + 1];
__device__ int g_cur[NMAX];
__device__ int g_src[EMAX];

__device__ __forceinline__ float warpSum(float v) {
#pragma unroll
    for (int o = 16; o; o >>= 1) v += __shfl_xor_sync(0xffffffffu, v, o);
    return v;
}

// ---------------- CSR build ----------------

__global__ void zero_kernel(int N) {
    int i = blockIdx.x * blockDim.x + threadIdx.x;
    if (i < N) g_cnt[i] = 0;
}

__global__ void count_kernel(const int* __restrict__ dst, int E) {
    int e = blockIdx.x * blockDim.x + threadIdx.x;
    if (e < E) atomicAdd(&g_cnt[dst[e]], 1);
}

__global__ void scan_kernel(int N) {
    __shared__ int s[1024];
    int t = threadIdx.x;
    int CH = (N + 1023) / 1024;
    int beg = t * CH;
    int end = beg + CH; if (end > N) end = N;
    if (beg > N) beg = N;
    int sum = 0;
    for (int i = beg; i < end; i++) sum += g_cnt[i];
    s[t] = sum;
    __syncthreads();
#pragma unroll
    for (int d = 1; d < 1024; d <<= 1) {
        int v = (t >= d) ? s[t - d] : 0;
        __syncthreads();
        if (t >= d) s[t] += v;
        __syncthreads();
    }
    int run = (t == 0) ? 0 : s[t - 1];
    for (int i = beg; i < end; i++) {
        g_off[i] = run;
        g_cur[i] = run;
        run += g_cnt[i];
    }
    if (t == 1023) g_off[N] = s[1023];
}

__global__ void scatter_kernel(const int* __restrict__ src, const int* __restrict__ dst, int E) {
    int e = blockIdx.x * blockDim.x + threadIdx.x;
    if (e < E) {
        int pos = atomicAdd(&g_cur[dst[e]], 1);
        g_src[pos] = src[e];
    }
}

// ---------------- Encoder: z = x[:, :2] @ enc_W + enc_b ----------------

__global__ void enc_kernel(const float* __restrict__ x, const float* __restrict__ W,
                           const float* __restrict__ b, int N) {
    int i = blockIdx.x * blockDim.x + threadIdx.x;
    if (i >= N * HD) return;
    int n = i >> 6, c = i & 63;
    g_z[i] = fmaf(x[n * 3], W[c], fmaf(x[n * 3 + 1], W[HD + c], b[c]));
}

// ---------------- Pre-norm: z = relu(LN(h, g, b)) ----------------

__global__ void __launch_bounds__(256) prenorm_kernel(const float* __restrict__ g,
                                                      const float* __restrict__ b, int N) {
    int gw = (blockIdx.x * 256 + threadIdx.x) >> 5;
    int lane = threadIdx.x & 31;
    if (gw >= N) return;
    float v0 = g_h[gw * HD + lane], v1 = g_h[gw * HD + lane + 32];
    float mean = warpSum(v0 + v1) * (1.0f / 64.0f);
    float d0 = v0 - mean, d1 = v1 - mean;
    float var = warpSum(d0 * d0 + d1 * d1) * (1.0f / 64.0f);
    float rstd = rsqrtf(var + 1e-5f);
    g_z[gw * HD + lane]      = fmaxf(fmaf(d0 * rstd, g[lane],      b[lane]),      0.0f);
    g_z[gw * HD + lane + 32] = fmaxf(fmaf(d1 * rstd, g[lane + 32], b[lane + 32]), 0.0f);
}

// ---------------- Softmax aggregation: y = softmax_aggr(z) + z ----------------
// one warp per dst node; 2 channels per lane; two passes (exact segment max)

__global__ void __launch_bounds__(256) aggr_kernel(const float* __restrict__ t, int layer, int N) {
    int gw = (blockIdx.x * 256 + threadIdx.x) >> 5;
    int lane = threadIdx.x & 31;
    if (gw >= N) return;
    float tl = __ldg(&t[layer]);
    int beg = g_off[gw], end = g_off[gw + 1];
    const float* __restrict__ z = g_z;
    float zi0 = z[gw * HD + lane], zi1 = z[gw * HD + lane + 32];
    float y0 = zi0, y1 = zi1;
    if (beg < end) {
        float m0 = -3.4e38f, m1 = -3.4e38f;
        for (int j = beg; j < end; j++) {
            int s = g_src[j] * HD;
            float v0 = fmaxf(z[s + lane], 0.0f) + 1e-7f;
            float v1 = fmaxf(z[s + lane + 32], 0.0f) + 1e-7f;
            m0 = fmaxf(m0, tl * v0);
            m1 = fmaxf(m1, tl * v1);
        }
        float den0 = 0.0f, den1 = 0.0f, acc0 = 0.0f, acc1 = 0.0f;
        for (int j = beg; j < end; j++) {
            int s = g_src[j] * HD;
            float v0 = fmaxf(z[s + lane], 0.0f) + 1e-7f;
            float v1 = fmaxf(z[s + lane + 32], 0.0f) + 1e-7f;
            float a0 = __expf(fmaf(tl, v0, -m0));
            float a1 = __expf(fmaf(tl, v1, -m1));
            den0 += a0; den1 += a1;
            acc0 = fmaf(a0, v0, acc0);
            acc1 = fmaf(a1, v1, acc1);
        }
        y0 += acc0 / den0;
        y1 += acc1 / den1;
    }
    g_y[gw * HD + lane] = y0;
    g_y[gw * HD + lane + 32] = y1;
}

// ---------------- Fused MLP: h (+)= relu(LN(y@W1+b1))@W2 + b2 ----------------
// persistent blocks; weights staged in dynamic smem; one warp per row at a time

#define MLP_NW 8
#define MLP_SMEM_FLOATS (8192 + 8192 + 128 + 128 + 128 + 64 + MLP_NW * 64 + MLP_NW * 128)

__global__ void __launch_bounds__(256, 1) mlp_kernel(
    const float* __restrict__ W1, const float* __restrict__ b1,
    const float* __restrict__ lg, const float* __restrict__ lb,
    const float* __restrict__ W2, const float* __restrict__ b2,
    int N, int add, int totalWarps) {
    extern __shared__ float smem[];
    float* sW1 = smem;                 // 8192
    float* sW2 = sW1 + 8192;           // 8192
    float* sb1 = sW2 + 8192;           // 128
    float* slg = sb1 + 128;            // 128
    float* slb = slg + 128;            // 128
    float* sb2 = slb + 128;            // 64
    float* sx  = sb2 + 64;             // MLP_NW*64
    float* sy  = sx + MLP_NW * 64;     // MLP_NW*128

    int tid = threadIdx.x;
    for (int i = tid; i < 8192; i += 256) sW1[i] = W1[i];
    for (int i = tid; i < 8192; i += 256) sW2[i] = W2[i];
    if (tid < 128) { sb1[tid] = b1[tid]; slg[tid] = lg[tid]; slb[tid] = lb[tid]; }
    if (tid < 64) sb2[tid] = b2[tid];
    __syncthreads();

    int w = tid >> 5, lane = tid & 31;
    int gw = blockIdx.x * MLP_NW + w;
    float* myx = sx + w * 64;
    float* myy = sy + w * 128;
    const float4* sW1v = (const float4*)sW1;
    const float2* sW2v = (const float2*)sW2;
    float2* h2 = (float2*)g_h;

    for (int r = gw; r < N; r += totalWarps) {
        myx[lane] = g_y[r * HD + lane];
        myx[lane + 32] = g_y[r * HD + lane + 32];
        __syncwarp();
        float a0 = 0, a1 = 0, a2 = 0, a3 = 0;
#pragma unroll
        for (int k = 0; k < 64; k++) {
            float xv = myx[k];
            float4 wv = sW1v[k * 32 + lane];
            a0 = fmaf(xv, wv.x, a0);
            a1 = fmaf(xv, wv.y, a1);
            a2 = fmaf(xv, wv.z, a2);
            a3 = fmaf(xv, wv.w, a3);
        }
        int j = lane * 4;
        a0 += sb1[j]; a1 += sb1[j + 1]; a2 += sb1[j + 2]; a3 += sb1[j + 3];
        float mean = warpSum(a0 + a1 + a2 + a3) * (1.0f / 128.0f);
        float d0 = a0 - mean, d1 = a1 - mean, d2 = a2 - mean, d3 = a3 - mean;
        float var = warpSum(d0 * d0 + d1 * d1 + d2 * d2 + d3 * d3) * (1.0f / 128.0f);
        float rstd = rsqrtf(var + 1e-5f);
        myy[j]     = fmaxf(fmaf(d0 * rstd, slg[j],     slb[j]),     0.0f);
        myy[j + 1] = fmaxf(fmaf(d1 * rstd, slg[j + 1], slb[j + 1]), 0.0f);
        myy[j + 2] = fmaxf(fmaf(d2 * rstd, slg[j + 2], slb[j + 2]), 0.0f);
        myy[j + 3] = fmaxf(fmaf(d3 * rstd, slg[j + 3], slb[j + 3]), 0.0f);
        __syncwarp();
        float c0 = 0, c1 = 0;
#pragma unroll
        for (int k = 0; k < 128; k++) {
            float yv = myy[k];
            float2 wv = sW2v[k * 32 + lane];
            c0 = fmaf(yv, wv.x, c0);
            c1 = fmaf(yv, wv.y, c1);
        }
        c0 += sb2[lane * 2];
        c1 += sb2[lane * 2 + 1];
        if (add) {
            float2 old = h2[r * 32 + lane];
            old.x += c0; old.y += c1;
            h2[r * 32 + lane] = old;
        } else {
            h2[r * 32 + lane] = make_float2(c0, c1);
        }
        __syncwarp();
    }
}

// ---------------- Head: pool -> fc -> bn -> l2norm ----------------

__global__ void __launch_bounds__(256) head_kernel(
    const float* __restrict__ fcW, const float* __restrict__ fcb,
    const float* __restrict__ bg, const float* __restrict__ bb,
    const float* __restrict__ bm, const float* __restrict__ bv,
    float* __restrict__ out, int NP) {
    __shared__ float shp[17 * 64];
    __shared__ float spool[6 * 64];
    __shared__ float sf[1536];
    __shared__ float sred[8];
    __shared__ float sinv;
    int p = blockIdx.x;
    int tid = threadIdx.x;
    for (int i = tid; i < 17 * 64; i += 256) shp[i] = g_z[p * (17 * 64) + i];
    __syncthreads();
    {
        const int ga[6] = {0, 0, 11, 0, 5, 11};
        const int gb[6] = {17, 11, 17, 5, 11, 17};
        for (int i = tid; i < 384; i += 256) {
            int s = i >> 6, c = i & 63;
            float acc = 0;
            for (int kp = ga[s]; kp < gb[s]; kp++) acc += shp[kp * 64 + c];
            spool[i] = acc / (float)(gb[s] - ga[s]);
        }
    }
    __syncthreads();
    float sq = 0;
#pragma unroll
    for (int s = 0; s < 6; s++) {
        int o = s * 256 + tid;
        float acc = fcb[o];
        const float* wp = fcW + s * 16384 + tid;
        const float* pp = spool + s * 64;
#pragma unroll 8
        for (int c = 0; c < 64; c++) acc = fmaf(pp[c], wp[c * 256], acc);
        float val = fmaf((acc - bm[o]) * rsqrtf(bv[o] + 1e-5f), bg[o], bb[o]);
        sf[o] = val;
        sq = fmaf(val, val, sq);
    }
    sq = warpSum(sq);
    if ((tid & 31) == 0) sred[tid >> 5] = sq;
    __syncthreads();
    if (tid == 0) {
        float tot = 0;
#pragma unroll
        for (int i = 0; i < 8; i++) tot += sred[i];
        float nrm = sqrtf(tot);
        sinv = 1.0f / fmaxf(nrm, 1e-12f);
    }
    __syncthreads();
    float inv = sinv;
#pragma unroll
    for (int s = 0; s < 6; s++) {
        int o = s * 256 + tid;
        out[p * 1536 + o] = sf[o] * inv;
    }
}

// ---------------- Host orchestration ----------------

extern "C" void kernel_launch(void* const* d_in, const int* in_sizes, int n_in,
                              void* d_out, int out_size) {
    const float* x      = (const float*)d_in[0];
    const int*   ei     = (const int*)d_in[1];
    const float* enc_W  = (const float*)d_in[2];
    const float* enc_b  = (const float*)d_in[3];
    const float* t      = (const float*)d_in[4];
    const float* mlp_W1 = (const float*)d_in[5];
    const float* mlp_b1 = (const float*)d_in[6];
    const float* ln_g   = (const float*)d_in[7];
    const float* ln_b   = (const float*)d_in[8];
    const float* mlp_W2 = (const float*)d_in[9];
    const float* mlp_b2 = (const float*)d_in[10];
    const float* norm_g = (const float*)d_in[11];
    const float* norm_b = (const float*)d_in[12];
    const float* fc_W   = (const float*)d_in[13];
    const float* fc_b   = (const float*)d_in[14];
    const float* bn_g   = (const float*)d_in[15];
    const float* bn_b   = (const float*)d_in[16];
    const float* bn_m   = (const float*)d_in[17];
    const float* bn_v   = (const float*)d_in[18];
    float* out = (float*)d_out;

    int N = in_sizes[0] / 3;
    int E = in_sizes[1] / 2;
    int NP = N / 17;
    const int L = 56;

    const int mlp_smem = MLP_SMEM_FLOATS * 4;
    cudaFuncSetAttribute(mlp_kernel, cudaFuncAttributeMaxDynamicSharedMemorySize, mlp_smem);

    // CSR build (dst-sorted)
    zero_kernel<<<(N + 255) / 256, 256>>>(N);
    count_kernel<<<(E + 255) / 256, 256>>>(ei + E, E);
    scan_kernel<<<1, 1024>>>(N);
    scatter_kernel<<<(E + 255) / 256, 256>>>(ei, ei + E, E);

    // Encoder -> z
    enc_kernel<<<(N * HD + 255) / 256, 256>>>(x, enc_W, enc_b, N);

    int aggrBlocks = (N + 7) / 8;  // one warp per node, 8 warps/block
    const int MLP_BLOCKS = 296;
    const int TW = MLP_BLOCKS * MLP_NW;

    // Layer 0 (replace h)
    aggr_kernel<<<aggrBlocks, 256>>>(t, 0, N);
    mlp_kernel<<<MLP_BLOCKS, 256, mlp_smem>>>(mlp_W1, mlp_b1, ln_g, ln_b, mlp_W2, mlp_b2,
                                              N, 0, TW);

    // Layers 1..55 (residual add)
    for (int l = 1; l < L; l++) {
        prenorm_kernel<<<aggrBlocks, 256>>>(norm_g + l * 64, norm_b + l * 64, N);
        aggr_kernel<<<aggrBlocks, 256>>>(t, l, N);
        mlp_kernel<<<MLP_BLOCKS, 256, mlp_smem>>>(
            mlp_W1 + l * 8192, mlp_b1 + l * 128,
            ln_g + l * 128, ln_b + l * 128,
            mlp_W2 + l * 8192, mlp_b2 + l * 64,
            N, 1, TW);
    }

    // Final pre-norm with layer-0 norm params
    prenorm_kernel<<<aggrBlocks, 256>>>(norm_g, norm_b, N);

    // Head
    head_kernel<<<NP, 256>>>(fc_W, fc_b, bn_g, bn_b, bn_m, bn_v, out, NP);
}

// round 3
// speedup vs baseline: 1.3965x; 1.3965x over previous
#include <cuda_runtime.h>
#include <math.h>

#define NMAX 34816
#define EMAX 557056

__device__ float g_h[NMAX * 64];
__device__ float g_z[NMAX * 64];
__device__ int g_cnt[NMAX];
__device__ int g_off[NMAX + 1];
__device__ int g_cur[NMAX];
__device__ int g_src[EMAX];

__device__ __forceinline__ float warpSum(float v) {
#pragma unroll
    for (int o = 16; o; o >>= 1) v += __shfl_xor_sync(0xffffffffu, v, o);
    return v;
}

// ---------------- CSR build ----------------

__global__ void zero_kernel(int N) {
    int i = blockIdx.x * blockDim.x + threadIdx.x;
    if (i < N) g_cnt[i] = 0;
}

__global__ void count_kernel(const int* __restrict__ dst, int E) {
    int e = blockIdx.x * blockDim.x + threadIdx.x;
    if (e < E) atomicAdd(&g_cnt[dst[e]], 1);
}

__global__ void scan_kernel(int N) {
    __shared__ int s[1024];
    int t = threadIdx.x;
    int CH = (N + 1023) / 1024;
    int beg = t * CH;
    int end = beg + CH; if (end > N) end = N;
    if (beg > N) beg = N;
    int sum = 0;
    for (int i = beg; i < end; i++) sum += g_cnt[i];
    s[t] = sum;
    __syncthreads();
#pragma unroll
    for (int d = 1; d < 1024; d <<= 1) {
        int v = (t >= d) ? s[t - d] : 0;
        __syncthreads();
        if (t >= d) s[t] += v;
        __syncthreads();
    }
    int run = (t == 0) ? 0 : s[t - 1];
    for (int i = beg; i < end; i++) {
        g_off[i] = run;
        g_cur[i] = run;
        run += g_cnt[i];
    }
    if (t == 1023) g_off[N] = s[1023];
}

__global__ void scatter_kernel(const int* __restrict__ src, const int* __restrict__ dst, int E) {
    int e = blockIdx.x * blockDim.x + threadIdx.x;
    if (e < E) {
        int pos = atomicAdd(&g_cur[dst[e]], 1);
        g_src[pos] = src[e];
    }
}

// ---------------- Encoder: z = x[:, :2] @ enc_W + enc_b ----------------

__global__ void enc_kernel(const float* __restrict__ x, const float* __restrict__ W,
                           const float* __restrict__ b, int N) {
    int i = blockIdx.x * blockDim.x + threadIdx.x;
    if (i >= N * 64) return;
    int n = i >> 6, c = i & 63;
    g_z[i] = fmaf(x[n * 3], W[c], fmaf(x[n * 3 + 1], W[64 + c], b[c]));
}

// ---------------- Pre-norm: z = relu(LN(h, g, b)) ----------------

__global__ void __launch_bounds__(256) prenorm_kernel(const float* __restrict__ g,
                                                      const float* __restrict__ b, int N) {
    int gw = (blockIdx.x * 256 + threadIdx.x) >> 5;
    int lane = threadIdx.x & 31;
    if (gw >= N) return;
    const float2* __restrict__ h2 = (const float2*)g_h;
    float2* z2 = (float2*)g_z;
    float2 v = h2[gw * 32 + lane];
    float mean = warpSum(v.x + v.y) * (1.0f / 64.0f);
    float dx = v.x - mean, dy = v.y - mean;
    float var = warpSum(dx * dx + dy * dy) * (1.0f / 64.0f);
    float rstd = rsqrtf(var + 1e-5f);
    float2 gg = ((const float2*)g)[lane];
    float2 bb = ((const float2*)b)[lane];
    float2 o;
    o.x = fmaxf(fmaf(dx * rstd, gg.x, bb.x), 0.0f);
    o.y = fmaxf(fmaf(dy * rstd, gg.y, bb.y), 0.0f);
    z2[gw * 32 + lane] = o;
}

// ---------------- Fused layer: softmax-aggregation + MLP + residual ----------------
// One warp handles 4 nodes: single-pass fixed-shift softmax aggregation (exact:
// the shift cancels in the acc/den ratio), then a register-blocked 4-row MLP
// (each smem weight read reused across 4 rows -> smem traffic / 4).
// h (+)= relu(LN(y@W1+b1))@W2 + b2,  y = aggr(z) + z

#define LAYER_SMEM_FLOATS (8192 + 8192 + 128 + 128 + 128 + 64 + 8 * 256 + 8 * 512)

__global__ void __launch_bounds__(256) layer_kernel(
    const float* __restrict__ W1, const float* __restrict__ b1,
    const float* __restrict__ lg, const float* __restrict__ lb,
    const float* __restrict__ W2, const float* __restrict__ b2,
    const float* __restrict__ t, int layer, int N, int add, int strideWarps) {
    extern __shared__ float smem[];
    float* sW1 = smem;                    // 8192
    float* sW2 = sW1 + 8192;              // 8192
    float* sb1 = sW2 + 8192;              // 128
    float* slg = sb1 + 128;               // 128
    float* slb = slg + 128;               // 128
    float* sb2 = slb + 128;               // 64
    float* sx  = sb2 + 64;                // 8 * 256
    float* sy  = sx + 8 * 256;            // 8 * 512

    int tid = threadIdx.x;
    {
        const float4* W1v = (const float4*)W1;
        const float4* W2v = (const float4*)W2;
        float4* d1 = (float4*)sW1;
        float4* d2 = (float4*)sW2;
        for (int i = tid; i < 2048; i += 256) { d1[i] = W1v[i]; d2[i] = W2v[i]; }
        if (tid < 128) { sb1[tid] = b1[tid]; slg[tid] = lg[tid]; slb[tid] = lb[tid]; }
        if (tid < 64) sb2[tid] = b2[tid];
    }
    __syncthreads();

    int w = tid >> 5, lane = tid & 31;
    float tl = __ldg(&t[layer]);
    const float2* __restrict__ z2 = (const float2*)g_z;
    float2* h2 = (float2*)g_h;
    float* myx = sx + w * 256;
    float* myy = sy + w * 512;
    const float4* sW1v = (const float4*)sW1;
    const float2* sW2v = (const float2*)sW2;
    float4 b14 = ((const float4*)sb1)[lane];
    float4 lg4 = ((const float4*)slg)[lane];
    float4 lb4 = ((const float4*)slb)[lane];
    float2 b22 = ((const float2*)sb2)[lane];

    int totalGroups = N >> 2;  // N % 4 == 0
    int warpId = blockIdx.x * 8 + w;

    for (int grp = warpId; grp < totalGroups; grp += strideWarps) {
        int r0 = grp * 4;
        // ---- aggregation for 4 nodes ----
#pragma unroll
        for (int ri = 0; ri < 4; ri++) {
            int node = r0 + ri;
            float2 zi = z2[node * 32 + lane];
            int beg = g_off[node], end = g_off[node + 1];
            float acc0 = 0.0f, acc1 = 0.0f, den0 = 0.0f, den1 = 0.0f;
#pragma unroll 2
            for (int j = beg; j < end; j++) {
                int s = g_src[j];
                float2 v = z2[s * 32 + lane];
                float v0 = fmaxf(v.x, 0.0f) + 1e-7f;
                float v1 = fmaxf(v.y, 0.0f) + 1e-7f;
                float a0 = __expf(fmaf(tl, v0, -4.0f));
                float a1 = __expf(fmaf(tl, v1, -4.0f));
                den0 += a0; den1 += a1;
                acc0 = fmaf(a0, v0, acc0);
                acc1 = fmaf(a1, v1, acc1);
            }
            float y0 = zi.x, y1 = zi.y;
            if (end > beg) { y0 += acc0 / den0; y1 += acc1 / den1; }
            myx[ri * 64 + 2 * lane] = y0;
            myx[ri * 64 + 2 * lane + 1] = y1;
        }
        __syncwarp();
        // ---- GEMM1: [4x64] @ [64x128], 16 accumulators per thread ----
        float a0[4] = {0, 0, 0, 0}, a1[4] = {0, 0, 0, 0};
        float a2[4] = {0, 0, 0, 0}, a3[4] = {0, 0, 0, 0};
#pragma unroll 4
        for (int k = 0; k < 64; k++) {
            float4 wv = sW1v[k * 32 + lane];
#pragma unroll
            for (int r = 0; r < 4; r++) {
                float xv = myx[r * 64 + k];
                a0[r] = fmaf(xv, wv.x, a0[r]);
                a1[r] = fmaf(xv, wv.y, a1[r]);
                a2[r] = fmaf(xv, wv.z, a2[r]);
                a3[r] = fmaf(xv, wv.w, a3[r]);
            }
        }
        // ---- bias + LN + relu per row ----
#pragma unroll
        for (int r = 0; r < 4; r++) {
            float v0 = a0[r] + b14.x, v1 = a1[r] + b14.y;
            float v2 = a2[r] + b14.z, v3 = a3[r] + b14.w;
            float mean = warpSum(v0 + v1 + v2 + v3) * (1.0f / 128.0f);
            float d0 = v0 - mean, d1 = v1 - mean, d2 = v2 - mean, d3 = v3 - mean;
            float var = warpSum(d0 * d0 + d1 * d1 + d2 * d2 + d3 * d3) * (1.0f / 128.0f);
            float rstd = rsqrtf(var + 1e-5f);
            float4 o;
            o.x = fmaxf(fmaf(d0 * rstd, lg4.x, lb4.x), 0.0f);
            o.y = fmaxf(fmaf(d1 * rstd, lg4.y, lb4.y), 0.0f);
            o.z = fmaxf(fmaf(d2 * rstd, lg4.z, lb4.z), 0.0f);
            o.w = fmaxf(fmaf(d3 * rstd, lg4.w, lb4.w), 0.0f);
            ((float4*)(myy + r * 128))[lane] = o;
        }
        __syncwarp();
        // ---- GEMM2: [4x128] @ [128x64] ----
        float c0[4] = {0, 0, 0, 0}, c1[4] = {0, 0, 0, 0};
#pragma unroll 4
        for (int k = 0; k < 128; k++) {
            float2 wv = sW2v[k * 32 + lane];
#pragma unroll
            for (int r = 0; r < 4; r++) {
                float yv = myy[r * 128 + k];
                c0[r] = fmaf(yv, wv.x, c0[r]);
                c1[r] = fmaf(yv, wv.y, c1[r]);
            }
        }
#pragma unroll
        for (int r = 0; r < 4; r++) {
            float2 o;
            o.x = c0[r] + b22.x;
            o.y = c1[r] + b22.y;
            if (add) {
                float2 old = h2[(r0 + r) * 32 + lane];
                o.x += old.x; o.y += old.y;
            }
            h2[(r0 + r) * 32 + lane] = o;
        }
        __syncwarp();
    }
}

// ---------------- Head: LN -> pool -> fc -> bn -> l2norm ----------------

__global__ void __launch_bounds__(256) head_kernel(
    const float* __restrict__ ng, const float* __restrict__ nb,
    const float* __restrict__ fcW, const float* __restrict__ fcb,
    const float* __restrict__ bg, const float* __restrict__ bb,
    const float* __restrict__ bm, const float* __restrict__ bv,
    float* __restrict__ out, int NP) {
    __shared__ float shp[17 * 64];
    __shared__ float spool[6 * 64];
    __shared__ float sf[1536];
    __shared__ float sred[8];
    __shared__ float sinv;
    int p = blockIdx.x;
    int tid = threadIdx.x;
    int w = tid >> 5, lane = tid & 31;
    const float2* __restrict__ h2 = (const float2*)g_h;
    float2 gg = ((const float2*)ng)[lane];
    float2 gb = ((const float2*)nb)[lane];
    for (int i = w; i < 17; i += 8) {
        float2 v = h2[(p * 17 + i) * 32 + lane];
        float mean = warpSum(v.x + v.y) * (1.0f / 64.0f);
        float dx = v.x - mean, dy = v.y - mean;
        float var = warpSum(dx * dx + dy * dy) * (1.0f / 64.0f);
        float rstd = rsqrtf(var + 1e-5f);
        shp[i * 64 + 2 * lane]     = fmaxf(fmaf(dx * rstd, gg.x, gb.x), 0.0f);
        shp[i * 64 + 2 * lane + 1] = fmaxf(fmaf(dy * rstd, gg.y, gb.y), 0.0f);
    }
    __syncthreads();
    {
        const int ga[6] = {0, 0, 11, 0, 5, 11};
        const int gbx[6] = {17, 11, 17, 5, 11, 17};
        for (int i = tid; i < 384; i += 256) {
            int s = i >> 6, c = i & 63;
            float acc = 0;
            for (int kp = ga[s]; kp < gbx[s]; kp++) acc += shp[kp * 64 + c];
            spool[i] = acc / (float)(gbx[s] - ga[s]);
        }
    }
    __syncthreads();
    float sq = 0;
#pragma unroll
    for (int s = 0; s < 6; s++) {
        int o = s * 256 + tid;
        float acc = fcb[o];
        const float* wp = fcW + s * 16384 + tid;
        const float* pp = spool + s * 64;
#pragma unroll 8
        for (int c = 0; c < 64; c++) acc = fmaf(pp[c], wp[c * 256], acc);
        float val = fmaf((acc - bm[o]) * rsqrtf(bv[o] + 1e-5f), bg[o], bb[o]);
        sf[o] = val;
        sq = fmaf(val, val, sq);
    }
    sq = warpSum(sq);
    if (lane == 0) sred[w] = sq;
    __syncthreads();
    if (tid == 0) {
        float tot = 0;
#pragma unroll
        for (int i = 0; i < 8; i++) tot += sred[i];
        sinv = 1.0f / fmaxf(sqrtf(tot), 1e-12f);
    }
    __syncthreads();
    float inv = sinv;
#pragma unroll
    for (int s = 0; s < 6; s++) {
        int o = s * 256 + tid;
        out[p * 1536 + o] = sf[o] * inv;
    }
}

// ---------------- Host orchestration ----------------

extern "C" void kernel_launch(void* const* d_in, const int* in_sizes, int n_in,
                              void* d_out, int out_size) {
    const float* x      = (const float*)d_in[0];
    const int*   ei     = (const int*)d_in[1];
    const float* enc_W  = (const float*)d_in[2];
    const float* enc_b  = (const float*)d_in[3];
    const float* t      = (const float*)d_in[4];
    const float* mlp_W1 = (const float*)d_in[5];
    const float* mlp_b1 = (const float*)d_in[6];
    const float* ln_g   = (const float*)d_in[7];
    const float* ln_b   = (const float*)d_in[8];
    const float* mlp_W2 = (const float*)d_in[9];
    const float* mlp_b2 = (const float*)d_in[10];
    const float* norm_g = (const float*)d_in[11];
    const float* norm_b = (const float*)d_in[12];
    const float* fc_W   = (const float*)d_in[13];
    const float* fc_b   = (const float*)d_in[14];
    const float* bn_g   = (const float*)d_in[15];
    const float* bn_b   = (const float*)d_in[16];
    const float* bn_m   = (const float*)d_in[17];
    const float* bn_v   = (const float*)d_in[18];
    float* out = (float*)d_out;

    int N = in_sizes[0] / 3;
    int E = in_sizes[1] / 2;
    int NP = N / 17;
    const int L = 56;

    const int layer_smem = LAYER_SMEM_FLOATS * 4;
    cudaFuncSetAttribute(layer_kernel, cudaFuncAttributeMaxDynamicSharedMemorySize, layer_smem);

    // CSR build (dst-sorted)
    zero_kernel<<<(N + 255) / 256, 256>>>(N);
    count_kernel<<<(E + 255) / 256, 256>>>(ei + E, E);
    scan_kernel<<<1, 1024>>>(N);
    scatter_kernel<<<(E + 255) / 256, 256>>>(ei, ei + E, E);

    // Encoder -> z
    enc_kernel<<<(N * 64 + 255) / 256, 256>>>(x, enc_W, enc_b, N);

    const int LB = 296;               // 2 blocks/SM
    const int SW = LB * 8;            // warps in grid
    int pnBlocks = (N + 7) / 8;

    // Layer 0 (replace h)
    layer_kernel<<<LB, 256, layer_smem>>>(mlp_W1, mlp_b1, ln_g, ln_b, mlp_W2, mlp_b2,
                                          t, 0, N, 0, SW);

    // Layers 1..55 (residual add)
    for (int l = 1; l < L; l++) {
        prenorm_kernel<<<pnBlocks, 256>>>(norm_g + l * 64, norm_b + l * 64, N);
        layer_kernel<<<LB, 256, layer_smem>>>(
            mlp_W1 + l * 8192, mlp_b1 + l * 128,
            ln_g + l * 128, ln_b + l * 128,
            mlp_W2 + l * 8192, mlp_b2 + l * 64,
            t, l, N, 1, SW);
    }

    // Head (applies final LN with layer-0 norm params internally)
    head_kernel<<<NP, 256>>>(norm_g, norm_b, fc_W, fc_b, bn_g, bn_b, bn_m, bn_v, out, NP);
}